// round 12
// baseline (speedup 1.0000x reference)
#include <cuda_runtime.h>
#include <cuda_bf16.h>
#include <math.h>
#include <stdint.h>

#define L 40
#define B 16
#define VSZ 10000
#define FDIM 512
#define HDIM 256
#define NPAIR 780
#define NROWS ((NPAIR + 1) * B)     // 12496
#define NPADROWS 12544              // 49 * 256
#define MTILE 256
#define NTILE 128
#define NMT (NPADROWS / MTILE)      // 49
#define NT_N 79                     // ceil(10000/128)
#define NPADN (NT_N * NTILE)        // 10112
#define YS 3                        // N-splits

#define DP_SMEM_BYTES ((L * L * B + 2 * NPAIR * B) * 4)   // 202,240 B

// word MMA smem layout (bytes); int8 tiles, 256 B/row + 16 pad
#define PITCHB 272
#define SM_A 0                       // 256*272 = 69632
#define SM_B 69632                   // 128*272 = 34816
#define SM_BIAS 104448               // 128 f32
#define SM_FSC  104960               // 128 f32
#define SM_TGT  105472               // 256 i32
#define SM_RED  106496               // 256*4 f32
#define WORD_SMEM (SM_RED + 4096)    // 110592

// prep kernel grid partition
#define PREP_TPAIR 780
#define PREP_HID   781
#define PREP_WCONV 316               // one block per 32 vocab columns
#define PREP_GRID  (PREP_TPAIR + PREP_HID + PREP_WCONV)

// ---------------- device scratch ----------------
__device__ float g_A1[L * B * HDIM];
__device__ float g_A2[L * B * HDIM];
__device__ float g_B1[L * B * HDIM];
__device__ float g_B2[L * B * HDIM];
__device__ float g_SH[NPAIR * B];
__device__ float g_RE[NPAIR * B];
__device__ signed char g_Hb[NPADROWS * HDIM];   // int8 hidden (pad rows stay 0)
__device__ signed char g_Wb[NPADN * HDIM];      // int8 Ww2 transposed [n][k]
__device__ float g_WSC[NPADN];                  // per-column dequant factor
__device__ float g_PS[YS * NPADROWS];           // partial sum-of-exp
__device__ float g_TG[NPADROWS];                // target logit
__device__ int   g_TGTI[NPADROWS];              // target vocab index per row

__device__ __forceinline__ void decode_pair(int p, int& i, int& j) {
    int ii = 0;
    while (p >= (L - 1) - ii) { p -= (L - 1) - ii; ++ii; }
    i = ii;
    j = ii + 1 + p;
}
__device__ __forceinline__ int pair_index(int i, int k) {
    return i * (L - 1) - (i * (i - 1)) / 2 + (k - i - 1);
}
__device__ __forceinline__ float logsig(float x) {
    return fminf(x, 0.f) - log1pf(__expf(-fabsf(x)));
}
__device__ __forceinline__ uint32_t smem_u32(const void* p) {
    uint32_t a;
    asm("{ .reg .u64 t; cvta.to.shared.u64 t, %1; cvt.u32.u64 %0, t; }" : "=r"(a) : "l"(p));
    return a;
}

#define LDSM_X4(r0, r1, r2, r3, addr)                                         \
    asm volatile("ldmatrix.sync.aligned.m8n8.x4.shared.b16 {%0,%1,%2,%3}, [%4];" \
                 : "=r"(r0), "=r"(r1), "=r"(r2), "=r"(r3) : "r"(addr))

#define MMA_S8(d, a, b0v, b1v)                                                \
    asm volatile("mma.sync.aligned.m16n8k32.row.col.s32.s8.s8.s32 "           \
                 "{%0,%1,%2,%3}, {%4,%5,%6,%7}, {%8,%9}, {%0,%1,%2,%3};"      \
                 : "+r"((d)[0]), "+r"((d)[1]), "+r"((d)[2]), "+r"((d)[3])     \
                 : "r"((a)[0]), "r"((a)[1]), "r"((a)[2]), "r"((a)[3]),        \
                   "r"(b0v), "r"(b1v))

// ---------------- 1) projection GEMMs ----------------
__global__ void proj_kernel(const float* __restrict__ h,
                            const float* __restrict__ Wt1,
                            const float* __restrict__ Ww1) {
    __shared__ float As[16][65];
    __shared__ float Bs[16][65];

    int which = blockIdx.z;
    const float* W = (which < 2) ? Ww1 : Wt1;
    const float* Wbase = W + ((which & 1) ? FDIM * HDIM : 0);
    float* C = (which == 0) ? g_A1 : (which == 1) ? g_A2 : (which == 2) ? g_B1 : g_B2;

    int tx = threadIdx.x;
    int m0 = blockIdx.x * 64;
    int n0 = blockIdx.y * 64;
    int tm = (tx >> 4) * 4;
    int tn = (tx & 15) * 4;

    float acc[4][4];
#pragma unroll
    for (int a = 0; a < 4; a++)
#pragma unroll
        for (int c = 0; c < 4; c++) acc[a][c] = 0.f;

    for (int k0 = 0; k0 < FDIM; k0 += 16) {
#pragma unroll
        for (int l = tx; l < 64 * 16; l += 256) {
            int mm = l >> 4, kk = l & 15;
            As[kk][mm] = h[(m0 + mm) * FDIM + k0 + kk];
        }
#pragma unroll
        for (int l = tx; l < 16 * 64; l += 256) {
            int kk = l >> 6, nn = l & 63;
            Bs[kk][nn] = Wbase[(k0 + kk) * HDIM + n0 + nn];
        }
        __syncthreads();
#pragma unroll
        for (int kk = 0; kk < 16; ++kk) {
            float a0 = As[kk][tm], a1 = As[kk][tm + 1], a2 = As[kk][tm + 2], a3 = As[kk][tm + 3];
            float b0 = Bs[kk][tn], b1 = Bs[kk][tn + 1], b2 = Bs[kk][tn + 2], b3 = Bs[kk][tn + 3];
            acc[0][0] = fmaf(a0, b0, acc[0][0]); acc[0][1] = fmaf(a0, b1, acc[0][1]);
            acc[0][2] = fmaf(a0, b2, acc[0][2]); acc[0][3] = fmaf(a0, b3, acc[0][3]);
            acc[1][0] = fmaf(a1, b0, acc[1][0]); acc[1][1] = fmaf(a1, b1, acc[1][1]);
            acc[1][2] = fmaf(a1, b2, acc[1][2]); acc[1][3] = fmaf(a1, b3, acc[1][3]);
            acc[2][0] = fmaf(a2, b0, acc[2][0]); acc[2][1] = fmaf(a2, b1, acc[2][1]);
            acc[2][2] = fmaf(a2, b2, acc[2][2]); acc[2][3] = fmaf(a2, b3, acc[2][3]);
            acc[3][0] = fmaf(a3, b0, acc[3][0]); acc[3][1] = fmaf(a3, b1, acc[3][1]);
            acc[3][2] = fmaf(a3, b2, acc[3][2]); acc[3][3] = fmaf(a3, b3, acc[3][3]);
        }
        __syncthreads();
    }
#pragma unroll
    for (int a = 0; a < 4; a++)
#pragma unroll
        for (int c = 0; c < 4; c++)
            C[(m0 + tm + a) * HDIM + n0 + tn + c] = acc[a][c];
}

// ---------------- 2) fused prep: tpair | hidden(int8) | wconv(int8 + scale) --
__global__ void prep_kernel(const float* __restrict__ bt1,
                            const float* __restrict__ Wt2,
                            const float* __restrict__ bt2,
                            const float* __restrict__ bw1,
                            const int* __restrict__ sentence,
                            const float* __restrict__ Ww2) {
    __shared__ float t[256][33];           // wconv staging (33 KB)
    __shared__ float red[8][33];
    int blk = blockIdx.x;
    int tid = threadIdx.x;

    if (blk < PREP_TPAIR) {
        int p = blk;
        int wid = tid >> 5, lane = tid & 31;
        int i, j;
        decode_pair(p, i, j);
#pragma unroll
        for (int sub = 0; sub < 2; ++sub) {
            int b = wid * 2 + sub;
            const float* r1 = g_B1 + (i * B + b) * HDIM;
            const float* r2 = g_B2 + (j * B + b) * HDIM;
            float acc = 0.f;
#pragma unroll
            for (int hh = lane; hh < HDIM; hh += 32) {
                float hv = tanhf(r1[hh] + r2[hh] + bt1[hh]);
                acc = fmaf(hv, Wt2[hh], acc);
            }
            acc += __shfl_xor_sync(~0u, acc, 16);
            acc += __shfl_xor_sync(~0u, acc, 8);
            acc += __shfl_xor_sync(~0u, acc, 4);
            acc += __shfl_xor_sync(~0u, acc, 2);
            acc += __shfl_xor_sync(~0u, acc, 1);
            if (lane == 0) {
                float tt = acc + bt2[0];
                g_SH[p * B + b] = logsig(-tt);
                g_RE[p * B + b] = logsig(tt);
            }
        }
    } else if (blk < PREP_TPAIR + PREP_HID) {
        int p = blk - PREP_TPAIR;
        int i = 0, j = 0;
        if (p < NPAIR) decode_pair(p, i, j);
#pragma unroll
        for (int bb = 0; bb < B; ++bb) {
            float v = tanhf(g_A1[(i * B + bb) * HDIM + tid]
                          + g_A2[(j * B + bb) * HDIM + tid] + bw1[tid]);
            g_Hb[(size_t)(p * B + bb) * HDIM + tid] =
                (signed char)__float2int_rn(v * 127.f);
        }
        if (tid < B) {
            int tg;
            if (p == NPAIR) tg = sentence[1 * B + tid];
            else {
                int j1 = (j + 1 < L) ? (j + 1) : (L - 1);
                tg = sentence[j1 * B + tid];
            }
            g_TGTI[p * B + tid] = tg;
        }
    } else {
        // wconv: 32 vocab columns per block, all 256 k
        int nt = blk - PREP_TPAIR - PREP_HID;   // 0..315
        int n0 = nt * 32;
        for (int idx = tid; idx < 256 * 32; idx += 256) {
            int k = idx >> 5, n = idx & 31;
            int gn = n0 + n;
            t[k][n] = (gn < VSZ) ? Ww2[k * VSZ + gn] : 0.f;
        }
        __syncthreads();
        int n = tid & 31, part = tid >> 5;
        float mx = 0.f;
#pragma unroll 4
        for (int kk = part * 32; kk < part * 32 + 32; ++kk)
            mx = fmaxf(mx, fabsf(t[kk][n]));
        red[part][n] = mx;
        __syncthreads();
        if (part == 0) {
            float m2 = red[0][n];
#pragma unroll
            for (int pp = 1; pp < 8; ++pp) m2 = fmaxf(m2, red[pp][n]);
            m2 = fmaxf(m2, 1e-8f);
            red[0][n] = 127.f / m2;                 // quant scale
            g_WSC[n0 + n] = m2 / (127.f * 127.f);   // dequant factor
        }
        __syncthreads();
        for (int idx = tid; idx < 32 * 256; idx += 256) {
            int nn = idx >> 8, k = idx & 255;
            float sw = red[0][nn];
            g_Wb[(size_t)(n0 + nn) * HDIM + k] =
                (signed char)__float2int_rn(t[k][nn] * sw);
        }
    }
}

// ---------------- 3) word GEMM via mma.sync s8 + fused softmax pieces --------
__global__ __launch_bounds__(512)
void wordmma_kernel(const float* __restrict__ bw2) {
    extern __shared__ char smem[];
    uint32_t sb = smem_u32(smem);
    float* bias_s = (float*)(smem + SM_BIAS);
    float* fsc_s  = (float*)(smem + SM_FSC);
    int*   tgt_s  = (int*)(smem + SM_TGT);
    float* red_s  = (float*)(smem + SM_RED);

    int tid = threadIdx.x;                 // 512
    int wid = tid >> 5, lane = tid & 31;
    int tq = lane & 3, gid = lane >> 2;
    int mt = blockIdx.x, ys = blockIdx.y;
    int warp_m = (wid & 3) * 64;           // 4 m-groups of 64
    int warp_n = (wid >> 2) * 32;          // 4 n-groups of 32

    // load A tile (256 x 256 s8) into smem, pitch 272 bytes
    {
        const signed char* hb = g_Hb + (size_t)mt * MTILE * HDIM;
        for (int idx = tid; idx < 256 * 16; idx += 512) {
            int r = idx >> 4, seg = idx & 15;
            uint4 v = *(const uint4*)(hb + (size_t)r * HDIM + seg * 16);
            *(uint4*)(smem + SM_A + r * PITCHB + seg * 16) = v;
        }
    }
    if (tid < 256) tgt_s[tid] = g_TGTI[mt * MTILE + tid];

    float rs[4][2];
#pragma unroll
    for (int mi = 0; mi < 4; ++mi) { rs[mi][0] = 0.f; rs[mi][1] = 0.f; }

    int nt0 = (ys * NT_N) / YS, nt1 = ((ys + 1) * NT_N) / YS;

    for (int nt = nt0; nt < nt1; ++nt) {
        int n0 = nt * NTILE;
        __syncthreads();    // previous iter's B reads done (also orders A stores)
        {
            const signed char* wb = g_Wb + (size_t)n0 * HDIM;
            for (int idx = tid; idx < 128 * 16; idx += 512) {
                int r = idx >> 4, seg = idx & 15;
                uint4 v = *(const uint4*)(wb + (size_t)r * HDIM + seg * 16);
                *(uint4*)(smem + SM_B + r * PITCHB + seg * 16) = v;
            }
        }
        if (tid < 128) {
            int col = n0 + tid;
            bias_s[tid] = (col < VSZ) ? bw2[col] : 0.f;
            fsc_s[tid] = g_WSC[n0 + tid];
        }
        __syncthreads();

        int d[4][4][4];
#pragma unroll
        for (int mi = 0; mi < 4; ++mi)
#pragma unroll
            for (int ni = 0; ni < 4; ++ni)
#pragma unroll
                for (int r = 0; r < 4; ++r) d[mi][ni][r] = 0;

#pragma unroll
        for (int ks = 0; ks < 8; ++ks) {
            int kb0 = ks * 32;
            uint32_t a[4][4];
#pragma unroll
            for (int mi = 0; mi < 4; ++mi) {
                uint32_t row = warp_m + mi * 16 + (lane & 15);
                uint32_t kb = kb0 + ((lane >> 4) << 4);
                uint32_t ad = sb + SM_A + row * PITCHB + kb;
                LDSM_X4(a[mi][0], a[mi][1], a[mi][2], a[mi][3], ad);
            }
#pragma unroll
            for (int nq = 0; nq < 2; ++nq) {
                uint32_t nrow = warp_n + nq * 16 + (lane & 7) + ((lane >> 4) << 3);
                uint32_t kb = kb0 + (((lane >> 3) & 1) << 4);
                uint32_t bd = sb + SM_B + nrow * PITCHB + kb;
                uint32_t bfr[4];
                LDSM_X4(bfr[0], bfr[1], bfr[2], bfr[3], bd);
#pragma unroll
                for (int mi = 0; mi < 4; ++mi) {
                    MMA_S8(d[mi][nq * 2 + 0], a[mi], bfr[0], bfr[1]);
                    MMA_S8(d[mi][nq * 2 + 1], a[mi], bfr[2], bfr[3]);
                }
            }
        }

        // epilogue: dequant + bias + exp-sum + target gather
#pragma unroll
        for (int mi = 0; mi < 4; ++mi) {
            int r0 = warp_m + mi * 16 + gid;
            int r1 = r0 + 8;
            int t0 = tgt_s[r0], t1 = tgt_s[r1];
            int grow0 = mt * MTILE + r0, grow1 = mt * MTILE + r1;
            float acc0 = 0.f, acc1 = 0.f;
#pragma unroll
            for (int ni = 0; ni < 4; ++ni) {
                int cl = warp_n + ni * 8 + tq * 2;
                int colb = n0 + cl;
                float f0 = fsc_s[cl], f1 = fsc_s[cl + 1];
                float bia0 = bias_s[cl], bia1 = bias_s[cl + 1];
                float v0 = (float)d[mi][ni][0] * f0 + bia0;
                float v1 = (float)d[mi][ni][1] * f1 + bia1;
                float v2 = (float)d[mi][ni][2] * f0 + bia0;
                float v3 = (float)d[mi][ni][3] * f1 + bia1;
                if (colb < VSZ) {
                    acc0 += __expf(v0);
                    acc1 += __expf(v2);
                    if (colb == t0) g_TG[grow0] = v0;
                    if (colb == t1) g_TG[grow1] = v2;
                }
                if (colb + 1 < VSZ) {
                    acc0 += __expf(v1);
                    acc1 += __expf(v3);
                    if (colb + 1 == t0) g_TG[grow0] = v1;
                    if (colb + 1 == t1) g_TG[grow1] = v3;
                }
            }
            rs[mi][0] += acc0;
            rs[mi][1] += acc1;
        }
    }

    // reduce rowsum across the 4 lanes of each row group
#pragma unroll
    for (int mi = 0; mi < 4; ++mi) {
#pragma unroll
        for (int hh = 0; hh < 2; ++hh) {
            float x = rs[mi][hh];
            x += __shfl_xor_sync(~0u, x, 1);
            x += __shfl_xor_sync(~0u, x, 2);
            if (tq == 0) {
                int row_l = warp_m + mi * 16 + gid + hh * 8;
                red_s[row_l * 4 + (wid >> 2)] = x;
            }
        }
    }
    __syncthreads();
    if (tid < 256) {
        float s = red_s[tid * 4 + 0] + red_s[tid * 4 + 1]
                + red_s[tid * 4 + 2] + red_s[tid * 4 + 3];
        g_PS[ys * NPADROWS + mt * MTILE + tid] = s;
    }
}

// ---------------- 4) CKY DP (fused fixup; smem; two-chain online LSE) --------
__global__ void dp_kernel(float* __restrict__ out) {
    extern __shared__ float sm[];
    float* T_s   = sm;
    float* SHW_s = sm + L * L * B;
    float* RE_s  = SHW_s + NPAIR * B;

    int tid = threadIdx.x;                 // 640
    int b = tid & 15, i = tid >> 4;

    // fused fixup: WLP = target - log(sum of 3 partials), folded into SHW
    for (int idx = tid; idx < NPAIR * B; idx += 640) {
        float s = g_PS[idx] + g_PS[NPADROWS + idx] + g_PS[2 * NPADROWS + idx];
        float wlp = g_TG[idx] - logf(s);
        SHW_s[idx] = g_SH[idx] + wlp;
        RE_s[idx]  = g_RE[idx];
    }
    if (i == 0) {
        int r = NPAIR * B + b;
        float s = g_PS[r] + g_PS[NPADROWS + r] + g_PS[2 * NPADROWS + r];
        T_s[(0 * L + 1) * B + b] = g_TG[r] - logf(s);
    } else if (i >= 1 && i <= 38) {
        T_s[(i * L + (i + 1)) * B + b] = 0.f;
    }
    __syncthreads();

    for (int gap = 2; gap <= L - 1; ++gap) {
        int n_i = L - gap;
        int j = i + gap;
        if (i < n_i) {
            float m0 = -1e30f, s0 = 0.f, m1 = -1e30f, s1 = 0.f;
            int k = i + 1;
            int pik = pair_index(i, k);
            for (; k + 1 < j; k += 2, pik += 2) {
                int pkj0 = pair_index(k, j);
                int pkj1 = pair_index(k + 1, j);
                float sc0 = T_s[(i * L + k) * B + b] + T_s[(k * L + j) * B + b]
                          + SHW_s[pik * B + b] + RE_s[pkj0 * B + b];
                float sc1 = T_s[(i * L + k + 1) * B + b] + T_s[((k + 1) * L + j) * B + b]
                          + SHW_s[(pik + 1) * B + b] + RE_s[pkj1 * B + b];
                float mn0 = fmaxf(m0, sc0);
                s0 = fmaf(s0, __expf(m0 - mn0), __expf(sc0 - mn0));
                m0 = mn0;
                float mn1 = fmaxf(m1, sc1);
                s1 = fmaf(s1, __expf(m1 - mn1), __expf(sc1 - mn1));
                m1 = mn1;
            }
            if (k < j) {
                int pkj0 = pair_index(k, j);
                float sc0 = T_s[(i * L + k) * B + b] + T_s[(k * L + j) * B + b]
                          + SHW_s[pik * B + b] + RE_s[pkj0 * B + b];
                float mn0 = fmaxf(m0, sc0);
                s0 = fmaf(s0, __expf(m0 - mn0), __expf(sc0 - mn0));
                m0 = mn0;
            }
            float mn = fmaxf(m0, m1);
            float ss = s0 * __expf(m0 - mn) + s1 * __expf(m1 - mn);
            T_s[(i * L + j) * B + b] = mn + logf(ss);
        }
        __syncthreads();
    }

    if (tid < B) out[tid] = T_s[(0 * L + (L - 1)) * B + tid];
}

// ---------------- launcher ----------------
extern "C" void kernel_launch(void* const* d_in, const int* in_sizes, int n_in,
                              void* d_out, int out_size) {
    const float* h        = (const float*)d_in[0];
    const int*   sentence = (const int*)d_in[1];
    const float* Wt1      = (const float*)d_in[2];
    const float* bt1      = (const float*)d_in[3];
    const float* Wt2      = (const float*)d_in[4];
    const float* bt2      = (const float*)d_in[5];
    const float* Ww1      = (const float*)d_in[6];
    const float* bw1      = (const float*)d_in[7];
    const float* Ww2      = (const float*)d_in[8];
    const float* bw2      = (const float*)d_in[9];
    float* out = (float*)d_out;

    static bool attr_set = false;
    if (!attr_set) {
        cudaFuncSetAttribute(dp_kernel, cudaFuncAttributeMaxDynamicSharedMemorySize,
                             DP_SMEM_BYTES);
        cudaFuncSetAttribute(wordmma_kernel, cudaFuncAttributeMaxDynamicSharedMemorySize,
                             WORD_SMEM);
        attr_set = true;
    }

    proj_kernel<<<dim3(10, 4, 4), 256>>>(h, Wt1, Ww1);
    prep_kernel<<<PREP_GRID, 256>>>(bt1, Wt2, bt2, bw1, sentence, Ww2);
    wordmma_kernel<<<dim3(NMT, YS), 512, WORD_SMEM>>>(bw2);
    dp_kernel<<<1, 640, DP_SMEM_BYTES>>>(out);
}

// round 13
// speedup vs baseline: 1.9175x; 1.9175x over previous
#include <cuda_runtime.h>
#include <cuda_bf16.h>
#include <math.h>
#include <stdint.h>

#define L 40
#define B 16
#define VSZ 10000
#define FDIM 512
#define HDIM 256
#define NPAIR 780
#define NROWS ((NPAIR + 1) * B)     // 12496
#define NPADROWS 12544              // 49 * 256
#define MTILE 256
#define NTILE 128
#define NMT (NPADROWS / MTILE)      // 49
#define NT_N 79                     // ceil(10000/128)
#define YS 3                        // N-splits

#define DP_SMEM_BYTES ((L * L * B + 2 * NPAIR * B) * 4)   // 202,240 B

// word MMA smem layout (bytes)
#define PITCH 264                    // halves per row (256 + 8 pad)
#define SM_A 0                       // 256 * 264 * 2 = 135168
#define SM_B 135168                  // 128 * 264 * 2 = 67584
#define SM_BIAS 202752               // 128 f32
#define SM_TGT  203264               // 256 i32
#define SM_RED  204288               // 256*4 f32 = 4096
#define WORD_SMEM (SM_RED + 4096)    // 208384

// prep kernel grid partition
#define PREP_TPAIR 780
#define PREP_HID   781
#define PREP_WCONV 2528              // 8 k-tiles x 316 n-tiles
#define PREP_GRID  (PREP_TPAIR + PREP_HID + PREP_WCONV)

// ---------------- device scratch ----------------
__device__ float g_A1[L * B * HDIM];
__device__ float g_A2[L * B * HDIM];
__device__ float g_B1[L * B * HDIM];
__device__ float g_B2[L * B * HDIM];
__device__ float g_SH[NPAIR * B];
__device__ float g_RE[NPAIR * B];
__device__ __nv_bfloat16 g_Hb[NPADROWS * HDIM];      // bf16 hidden (pad rows stay 0)
__device__ __nv_bfloat16 g_Wb[NT_N * NTILE * HDIM];  // bf16 Ww2 transposed [n][k]
__device__ float g_PS[YS * NPADROWS];                // partial sum-of-exp
__device__ float g_TG[NPADROWS];                     // target logit
__device__ int   g_TGTI[NPADROWS];                   // target vocab index per row

__device__ __forceinline__ void decode_pair(int p, int& i, int& j) {
    int ii = 0;
    while (p >= (L - 1) - ii) { p -= (L - 1) - ii; ++ii; }
    i = ii;
    j = ii + 1 + p;
}
__device__ __forceinline__ int pair_index(int i, int k) {
    return i * (L - 1) - (i * (i - 1)) / 2 + (k - i - 1);
}
__device__ __forceinline__ float logsig(float x) {
    return fminf(x, 0.f) - log1pf(__expf(-fabsf(x)));
}
__device__ __forceinline__ uint32_t smem_u32(const void* p) {
    uint32_t a;
    asm("{ .reg .u64 t; cvta.to.shared.u64 t, %1; cvt.u32.u64 %0, t; }" : "=r"(a) : "l"(p));
    return a;
}

#define LDSM_X4(r0, r1, r2, r3, addr)                                         \
    asm volatile("ldmatrix.sync.aligned.m8n8.x4.shared.b16 {%0,%1,%2,%3}, [%4];" \
                 : "=r"(r0), "=r"(r1), "=r"(r2), "=r"(r3) : "r"(addr))

#define MMA_BF16(d, a, b0v, b1v)                                              \
    asm volatile("mma.sync.aligned.m16n8k16.row.col.f32.bf16.bf16.f32 "       \
                 "{%0,%1,%2,%3}, {%4,%5,%6,%7}, {%8,%9}, {%0,%1,%2,%3};"      \
                 : "+f"((d)[0]), "+f"((d)[1]), "+f"((d)[2]), "+f"((d)[3])     \
                 : "r"((a)[0]), "r"((a)[1]), "r"((a)[2]), "r"((a)[3]),        \
                   "r"(b0v), "r"(b1v))

// ---------------- 1) projection GEMMs ----------------
__global__ void proj_kernel(const float* __restrict__ h,
                            const float* __restrict__ Wt1,
                            const float* __restrict__ Ww1) {
    __shared__ float As[16][65];
    __shared__ float Bs[16][65];

    int which = blockIdx.z;
    const float* W = (which < 2) ? Ww1 : Wt1;
    const float* Wbase = W + ((which & 1) ? FDIM * HDIM : 0);
    float* C = (which == 0) ? g_A1 : (which == 1) ? g_A2 : (which == 2) ? g_B1 : g_B2;

    int tx = threadIdx.x;
    int m0 = blockIdx.x * 64;
    int n0 = blockIdx.y * 64;
    int tm = (tx >> 4) * 4;
    int tn = (tx & 15) * 4;

    float acc[4][4];
#pragma unroll
    for (int a = 0; a < 4; a++)
#pragma unroll
        for (int c = 0; c < 4; c++) acc[a][c] = 0.f;

    for (int k0 = 0; k0 < FDIM; k0 += 16) {
#pragma unroll
        for (int l = tx; l < 64 * 16; l += 256) {
            int mm = l >> 4, kk = l & 15;
            As[kk][mm] = h[(m0 + mm) * FDIM + k0 + kk];
        }
#pragma unroll
        for (int l = tx; l < 16 * 64; l += 256) {
            int kk = l >> 6, nn = l & 63;
            Bs[kk][nn] = Wbase[(k0 + kk) * HDIM + n0 + nn];
        }
        __syncthreads();
#pragma unroll
        for (int kk = 0; kk < 16; ++kk) {
            float a0 = As[kk][tm], a1 = As[kk][tm + 1], a2 = As[kk][tm + 2], a3 = As[kk][tm + 3];
            float b0 = Bs[kk][tn], b1 = Bs[kk][tn + 1], b2 = Bs[kk][tn + 2], b3 = Bs[kk][tn + 3];
            acc[0][0] = fmaf(a0, b0, acc[0][0]); acc[0][1] = fmaf(a0, b1, acc[0][1]);
            acc[0][2] = fmaf(a0, b2, acc[0][2]); acc[0][3] = fmaf(a0, b3, acc[0][3]);
            acc[1][0] = fmaf(a1, b0, acc[1][0]); acc[1][1] = fmaf(a1, b1, acc[1][1]);
            acc[1][2] = fmaf(a1, b2, acc[1][2]); acc[1][3] = fmaf(a1, b3, acc[1][3]);
            acc[2][0] = fmaf(a2, b0, acc[2][0]); acc[2][1] = fmaf(a2, b1, acc[2][1]);
            acc[2][2] = fmaf(a2, b2, acc[2][2]); acc[2][3] = fmaf(a2, b3, acc[2][3]);
            acc[3][0] = fmaf(a3, b0, acc[3][0]); acc[3][1] = fmaf(a3, b1, acc[3][1]);
            acc[3][2] = fmaf(a3, b2, acc[3][2]); acc[3][3] = fmaf(a3, b3, acc[3][3]);
        }
        __syncthreads();
    }
#pragma unroll
    for (int a = 0; a < 4; a++)
#pragma unroll
        for (int c = 0; c < 4; c++)
            C[(m0 + tm + a) * HDIM + n0 + tn + c] = acc[a][c];
}

// ---------------- 2) fused prep: tpair | hiddenb | wconv (grid-partitioned) --
__global__ void prep_kernel(const float* __restrict__ bt1,
                            const float* __restrict__ Wt2,
                            const float* __restrict__ bt2,
                            const float* __restrict__ bw1,
                            const int* __restrict__ sentence,
                            const float* __restrict__ Ww2) {
    __shared__ float t[32][33];
    int blk = blockIdx.x;
    int tid = threadIdx.x;

    if (blk < PREP_TPAIR) {
        int p = blk;
        int wid = tid >> 5, lane = tid & 31;
        int i, j;
        decode_pair(p, i, j);
#pragma unroll
        for (int sub = 0; sub < 2; ++sub) {
            int b = wid * 2 + sub;
            const float* r1 = g_B1 + (i * B + b) * HDIM;
            const float* r2 = g_B2 + (j * B + b) * HDIM;
            float acc = 0.f;
#pragma unroll
            for (int hh = lane; hh < HDIM; hh += 32) {
                float hv = tanhf(r1[hh] + r2[hh] + bt1[hh]);
                acc = fmaf(hv, Wt2[hh], acc);
            }
            acc += __shfl_xor_sync(~0u, acc, 16);
            acc += __shfl_xor_sync(~0u, acc, 8);
            acc += __shfl_xor_sync(~0u, acc, 4);
            acc += __shfl_xor_sync(~0u, acc, 2);
            acc += __shfl_xor_sync(~0u, acc, 1);
            if (lane == 0) {
                float tt = acc + bt2[0];
                g_SH[p * B + b] = logsig(-tt);
                g_RE[p * B + b] = logsig(tt);
            }
        }
    } else if (blk < PREP_TPAIR + PREP_HID) {
        int p = blk - PREP_TPAIR;
        int i = 0, j = 0;
        if (p < NPAIR) decode_pair(p, i, j);
#pragma unroll
        for (int bb = 0; bb < B; ++bb) {
            float v = tanhf(g_A1[(i * B + bb) * HDIM + tid]
                          + g_A2[(j * B + bb) * HDIM + tid] + bw1[tid]);
            g_Hb[(p * B + bb) * HDIM + tid] = __float2bfloat16(v);
        }
        if (tid < B) {
            int tg;
            if (p == NPAIR) tg = sentence[1 * B + tid];
            else {
                int j1 = (j + 1 < L) ? (j + 1) : (L - 1);
                tg = sentence[j1 * B + tid];
            }
            g_TGTI[p * B + tid] = tg;
        }
    } else {
        int tile = blk - PREP_TPAIR - PREP_HID;
        int kt = tile & 7;
        int nt = tile >> 3;
        int tx = tid & 31, ty0 = tid >> 5;
#pragma unroll
        for (int rr = 0; rr < 4; ++rr) {
            int ty = ty0 + rr * 8;
            int k = kt * 32 + ty, n = nt * 32 + tx;
            t[ty][tx] = (n < VSZ) ? Ww2[k * VSZ + n] : 0.f;
        }
        __syncthreads();
#pragma unroll
        for (int rr = 0; rr < 4; ++rr) {
            int ty = ty0 + rr * 8;
            int n2 = nt * 32 + ty, k2 = kt * 32 + tx;
            g_Wb[n2 * HDIM + k2] = __float2bfloat16(t[tx][ty]);
        }
    }
}

// ---------------- 3) word GEMM via mma.sync bf16 + fused softmax pieces ------
__global__ __launch_bounds__(512)
void wordmma_kernel(const float* __restrict__ bw2) {
    extern __shared__ char smem[];
    uint32_t sb = smem_u32(smem);
    float* bias_s = (float*)(smem + SM_BIAS);
    int*   tgt_s  = (int*)(smem + SM_TGT);
    float* red_s  = (float*)(smem + SM_RED);

    int tid = threadIdx.x;                 // 512
    int wid = tid >> 5, lane = tid & 31;
    int tq = lane & 3, gid = lane >> 2;
    int mt = blockIdx.x, ys = blockIdx.y;
    int warp_m = (wid & 3) * 64;           // 4 m-groups
    int warp_n = (wid >> 2) * 32;          // 4 n-groups

    // load A tile (256 x 256 bf16) into smem, pitch 264 halves
    {
        const __nv_bfloat16* hb = g_Hb + (size_t)mt * MTILE * HDIM;
        for (int idx = tid; idx < 256 * 32; idx += 512) {
            int r = idx >> 5, seg = idx & 31;
            uint4 v = *(const uint4*)(hb + r * HDIM + seg * 8);
            *(uint4*)(smem + SM_A + (r * PITCH + seg * 8) * 2) = v;
        }
    }
    if (tid < 256) tgt_s[tid] = g_TGTI[mt * MTILE + tid];

    float rs[4][2];
#pragma unroll
    for (int mi = 0; mi < 4; ++mi) { rs[mi][0] = 0.f; rs[mi][1] = 0.f; }

    int nt0 = (ys * NT_N) / YS, nt1 = ((ys + 1) * NT_N) / YS;

    // prologue: prefetch first B tile into registers (8 x uint4 per thread)
    uint4 pre[8];
    {
        const __nv_bfloat16* wb = g_Wb + (size_t)nt0 * NTILE * HDIM;
#pragma unroll
        for (int u = 0; u < 8; ++u) {
            int idx = tid + u * 512;
            int r = idx >> 5, seg = idx & 31;
            pre[u] = *(const uint4*)(wb + r * HDIM + seg * 8);
        }
    }

    for (int nt = nt0; nt < nt1; ++nt) {
        int n0 = nt * NTILE;
        __syncthreads();    // previous iter's smem B reads done (also orders A stores)
#pragma unroll
        for (int u = 0; u < 8; ++u) {
            int idx = tid + u * 512;
            int r = idx >> 5, seg = idx & 31;
            *(uint4*)(smem + SM_B + (r * PITCH + seg * 8) * 2) = pre[u];
        }
        if (tid < 128) {
            int col = n0 + tid;
            bias_s[tid] = (col < VSZ) ? bw2[col] : 0.f;
        }
        __syncthreads();

        // prefetch next B tile into registers (overlaps with MMA below)
        if (nt + 1 < nt1) {
            const __nv_bfloat16* wb = g_Wb + (size_t)(nt + 1) * NTILE * HDIM;
#pragma unroll
            for (int u = 0; u < 8; ++u) {
                int idx = tid + u * 512;
                int r = idx >> 5, seg = idx & 31;
                pre[u] = *(const uint4*)(wb + r * HDIM + seg * 8);
            }
        }

        float d[4][4][4];
#pragma unroll
        for (int mi = 0; mi < 4; ++mi)
#pragma unroll
            for (int ni = 0; ni < 4; ++ni)
#pragma unroll
                for (int r = 0; r < 4; ++r) d[mi][ni][r] = 0.f;

#pragma unroll
        for (int ks = 0; ks < 16; ++ks) {
            int k0 = ks * 16;
            uint32_t a[4][4];
#pragma unroll
            for (int mi = 0; mi < 4; ++mi) {
                uint32_t row = warp_m + mi * 16 + (lane & 15);
                uint32_t col = k0 + ((lane >> 4) << 3);
                uint32_t ad = sb + SM_A + (row * PITCH + col) * 2;
                LDSM_X4(a[mi][0], a[mi][1], a[mi][2], a[mi][3], ad);
            }
#pragma unroll
            for (int nq = 0; nq < 2; ++nq) {
                uint32_t nrow = warp_n + nq * 16 + (lane & 7) + ((lane >> 4) << 3);
                uint32_t col = k0 + (((lane >> 3) & 1) << 3);
                uint32_t bd = sb + SM_B + (nrow * PITCH + col) * 2;
                uint32_t bfr[4];
                LDSM_X4(bfr[0], bfr[1], bfr[2], bfr[3], bd);
#pragma unroll
                for (int mi = 0; mi < 4; ++mi) {
                    MMA_BF16(d[mi][nq * 2 + 0], a[mi], bfr[0], bfr[1]);
                    MMA_BF16(d[mi][nq * 2 + 1], a[mi], bfr[2], bfr[3]);
                }
            }
        }

        // epilogue: bias + exp-sum + target gather
#pragma unroll
        for (int mi = 0; mi < 4; ++mi) {
            int r0 = warp_m + mi * 16 + gid;
            int r1 = r0 + 8;
            int t0 = tgt_s[r0], t1 = tgt_s[r1];
            int grow0 = mt * MTILE + r0, grow1 = mt * MTILE + r1;
            float acc0 = 0.f, acc1 = 0.f;
#pragma unroll
            for (int ni = 0; ni < 4; ++ni) {
                int cl = warp_n + ni * 8 + tq * 2;
                int colb = n0 + cl;
                float bia0 = bias_s[cl], bia1 = bias_s[cl + 1];
                float v0 = d[mi][ni][0] + bia0;
                float v1 = d[mi][ni][1] + bia1;
                float v2 = d[mi][ni][2] + bia0;
                float v3 = d[mi][ni][3] + bia1;
                if (colb < VSZ) {
                    acc0 += __expf(v0);
                    acc1 += __expf(v2);
                    if (colb == t0) g_TG[grow0] = v0;
                    if (colb == t1) g_TG[grow1] = v2;
                }
                if (colb + 1 < VSZ) {
                    acc0 += __expf(v1);
                    acc1 += __expf(v3);
                    if (colb + 1 == t0) g_TG[grow0] = v1;
                    if (colb + 1 == t1) g_TG[grow1] = v3;
                }
            }
            rs[mi][0] += acc0;
            rs[mi][1] += acc1;
        }
    }

    // reduce rowsum across the 4 lanes of each row group
#pragma unroll
    for (int mi = 0; mi < 4; ++mi) {
#pragma unroll
        for (int hh = 0; hh < 2; ++hh) {
            float x = rs[mi][hh];
            x += __shfl_xor_sync(~0u, x, 1);
            x += __shfl_xor_sync(~0u, x, 2);
            if (tq == 0) {
                int row_l = warp_m + mi * 16 + gid + hh * 8;
                red_s[row_l * 4 + (wid >> 2)] = x;
            }
        }
    }
    __syncthreads();
    if (tid < 256) {
        float s = red_s[tid * 4 + 0] + red_s[tid * 4 + 1]
                + red_s[tid * 4 + 2] + red_s[tid * 4 + 3];
        g_PS[ys * NPADROWS + mt * MTILE + tid] = s;
    }
}

// ---------------- 4) CKY DP (fused fixup; smem; two-chain online LSE) --------
__global__ void dp_kernel(float* __restrict__ out) {
    extern __shared__ float sm[];
    float* T_s   = sm;
    float* SHW_s = sm + L * L * B;
    float* RE_s  = SHW_s + NPAIR * B;

    int tid = threadIdx.x;                 // 640
    int b = tid & 15, i = tid >> 4;

    // fused fixup: WLP = target - log(sum of 3 partials), folded into SHW
    for (int idx = tid; idx < NPAIR * B; idx += 640) {
        float s = g_PS[idx] + g_PS[NPADROWS + idx] + g_PS[2 * NPADROWS + idx];
        float wlp = g_TG[idx] - logf(s);
        SHW_s[idx] = g_SH[idx] + wlp;
        RE_s[idx]  = g_RE[idx];
    }
    if (i == 0) {
        int r = NPAIR * B + b;
        float s = g_PS[r] + g_PS[NPADROWS + r] + g_PS[2 * NPADROWS + r];
        T_s[(0 * L + 1) * B + b] = g_TG[r] - logf(s);
    } else if (i >= 1 && i <= 38) {
        T_s[(i * L + (i + 1)) * B + b] = 0.f;
    }
    __syncthreads();

    for (int gap = 2; gap <= L - 1; ++gap) {
        int n_i = L - gap;
        int j = i + gap;
        if (i < n_i) {
            float m0 = -1e30f, s0 = 0.f, m1 = -1e30f, s1 = 0.f;
            int k = i + 1;
            int pik = pair_index(i, k);
            for (; k + 1 < j; k += 2, pik += 2) {
                int pkj0 = pair_index(k, j);
                int pkj1 = pair_index(k + 1, j);
                float sc0 = T_s[(i * L + k) * B + b] + T_s[(k * L + j) * B + b]
                          + SHW_s[pik * B + b] + RE_s[pkj0 * B + b];
                float sc1 = T_s[(i * L + k + 1) * B + b] + T_s[((k + 1) * L + j) * B + b]
                          + SHW_s[(pik + 1) * B + b] + RE_s[pkj1 * B + b];
                float mn0 = fmaxf(m0, sc0);
                s0 = fmaf(s0, __expf(m0 - mn0), __expf(sc0 - mn0));
                m0 = mn0;
                float mn1 = fmaxf(m1, sc1);
                s1 = fmaf(s1, __expf(m1 - mn1), __expf(sc1 - mn1));
                m1 = mn1;
            }
            if (k < j) {
                int pkj0 = pair_index(k, j);
                float sc0 = T_s[(i * L + k) * B + b] + T_s[(k * L + j) * B + b]
                          + SHW_s[pik * B + b] + RE_s[pkj0 * B + b];
                float mn0 = fmaxf(m0, sc0);
                s0 = fmaf(s0, __expf(m0 - mn0), __expf(sc0 - mn0));
                m0 = mn0;
            }
            float mn = fmaxf(m0, m1);
            float ss = s0 * __expf(m0 - mn) + s1 * __expf(m1 - mn);
            T_s[(i * L + j) * B + b] = mn + logf(ss);
        }
        __syncthreads();
    }

    if (tid < B) out[tid] = T_s[(0 * L + (L - 1)) * B + tid];
}

// ---------------- launcher ----------------
extern "C" void kernel_launch(void* const* d_in, const int* in_sizes, int n_in,
                              void* d_out, int out_size) {
    const float* h        = (const float*)d_in[0];
    const int*   sentence = (const int*)d_in[1];
    const float* Wt1      = (const float*)d_in[2];
    const float* bt1      = (const float*)d_in[3];
    const float* Wt2      = (const float*)d_in[4];
    const float* bt2      = (const float*)d_in[5];
    const float* Ww1      = (const float*)d_in[6];
    const float* bw1      = (const float*)d_in[7];
    const float* Ww2      = (const float*)d_in[8];
    const float* bw2      = (const float*)d_in[9];
    float* out = (float*)d_out;

    static bool attr_set = false;
    if (!attr_set) {
        cudaFuncSetAttribute(dp_kernel, cudaFuncAttributeMaxDynamicSharedMemorySize,
                             DP_SMEM_BYTES);
        cudaFuncSetAttribute(wordmma_kernel, cudaFuncAttributeMaxDynamicSharedMemorySize,
                             WORD_SMEM);
        attr_set = true;
    }

    proj_kernel<<<dim3(10, 4, 4), 256>>>(h, Wt1, Ww1);
    prep_kernel<<<PREP_GRID, 256>>>(bt1, Wt2, bt2, bw1, sentence, Ww2);
    wordmma_kernel<<<dim3(NMT, YS), 512, WORD_SMEM>>>(bw2);
    dp_kernel<<<1, 640, DP_SMEM_BYTES>>>(out);
}